// round 1
// baseline (speedup 1.0000x reference)
#include <cuda_runtime.h>
#include <math.h>

#define B_  2
#define S_  2048
#define D_  1024
#define H_  16
#define DH  64
#define M_  (B_*S_)
#define SCALE 0.03125f   // 1024^-0.5

// Scratch (allocation-free rule: __device__ globals)
__device__ float g_Q[M_*D_];
__device__ float g_K[M_*D_];
__device__ float g_V[M_*D_];
__device__ float g_A[M_*D_];

// ---------------------------------------------------------------------------
// GEMM: C[M,N] = A[M,K] @ W[K,N] + bias[N]   (all row-major fp32)
// 64x64 block tile, BK=16, 256 threads, 4x4 register blocking.
// ---------------------------------------------------------------------------
__global__ __launch_bounds__(256) void gemm_bias_kernel(
    const float* __restrict__ A, const float* __restrict__ W,
    const float* __restrict__ bias, float* __restrict__ C,
    int M, int N, int K)
{
    __shared__ float As[16][65];   // [k][m], pad 65 kills 16-way store conflict
    __shared__ float Bs[16][64];   // [k][n]

    const int t  = threadIdx.x;
    const int tx = t & 15;         // n-group
    const int ty = t >> 4;         // m-group
    const int row0 = blockIdx.y * 64;
    const int col0 = blockIdx.x * 64;

    float acc[4][4] = {};

    for (int k0 = 0; k0 < K; k0 += 16) {
        #pragma unroll
        for (int i = 0; i < 4; i++) {
            int idx = t + i * 256;          // 1024 elems of A tile
            int m  = idx >> 4;
            int kk = idx & 15;
            As[kk][m] = A[(size_t)(row0 + m) * K + (k0 + kk)];
        }
        #pragma unroll
        for (int i = 0; i < 4; i++) {
            int idx = t + i * 256;          // 1024 elems of B tile
            int kk = idx >> 6;
            int n  = idx & 63;
            Bs[kk][n] = W[(size_t)(k0 + kk) * N + (col0 + n)];
        }
        __syncthreads();

        #pragma unroll
        for (int kk = 0; kk < 16; kk++) {
            float a[4], b[4];
            #pragma unroll
            for (int i = 0; i < 4; i++) a[i] = As[kk][ty * 4 + i];
            #pragma unroll
            for (int j = 0; j < 4; j++) b[j] = Bs[kk][tx * 4 + j];
            #pragma unroll
            for (int i = 0; i < 4; i++)
                #pragma unroll
                for (int j = 0; j < 4; j++)
                    acc[i][j] = fmaf(a[i], b[j], acc[i][j]);
        }
        __syncthreads();
    }

    #pragma unroll
    for (int i = 0; i < 4; i++) {
        int r = row0 + ty * 4 + i;
        #pragma unroll
        for (int j = 0; j < 4; j++) {
            int c = col0 + tx * 4 + j;
            C[(size_t)r * N + c] = acc[i][j] + bias[c];
        }
    }
}

// ---------------------------------------------------------------------------
// Flash-attention (causal), fp32. One CTA per (b, h, 64-query tile).
// 128 threads. Per 64-key tile:
//   phase 1: S = Q K^T (4x8 register-blocked outer product) -> smem (masked)
//   phase 2: per-query online softmax; 2 threads/query, each owns d/2 = 32
//            output accumulators in registers.
// ---------------------------------------------------------------------------
#define QTILE 64
#define KTILE 64
#define PAD   68   // padded row stride (floats): 4-aligned for float4, conflict-light

// smem layout (floats):
//   QsT [DH][PAD]   (Q transposed, pre-scaled)
//   KsT [DH][PAD]   (K transposed)
//   Vs  [KTILE][DH]
//   Ss  [QTILE][PAD]
#define SMEM_FLOATS (DH*PAD + DH*PAD + KTILE*DH + QTILE*PAD)

__global__ __launch_bounds__(128) void attn_kernel(
    const float* __restrict__ Q, const float* __restrict__ K,
    const float* __restrict__ V, float* __restrict__ O)
{
    extern __shared__ float smem[];
    float* QsT = smem;                 // [DH][PAD]
    float* KsT = QsT + DH * PAD;       // [DH][PAD]
    float* Vs  = KsT + DH * PAD;       // [KTILE][DH]
    float* Ss  = Vs  + KTILE * DH;     // [QTILE][PAD]

    const int t  = threadIdx.x;
    const int qt = blockIdx.x;         // query tile 0..31
    const int h  = blockIdx.y;
    const int b  = blockIdx.z;

    const size_t base = (size_t)b * S_ * D_ + (size_t)h * DH;  // + s*D_ + dd
    const int q0 = qt * QTILE;

    // Load Q tile, transposed + pre-scaled
    for (int idx = t; idx < QTILE * DH; idx += 128) {
        int q  = idx >> 6;
        int dd = idx & 63;
        QsT[dd * PAD + q] = Q[base + (size_t)(q0 + q) * D_ + dd] * SCALE;
    }

    // phase-1 mapping: 16 q-groups x 8 j-groups
    const int qg = t >> 3;   // queries qg*4 .. +3
    const int jg = t & 7;    // keys    jg*8 .. +7
    // phase-2 mapping: 2 threads per query
    const int qi   = t >> 1;
    const int half = t & 1;

    float m = -1e30f, l = 0.f;
    float o[32];
    #pragma unroll
    for (int i = 0; i < 32; i++) o[i] = 0.f;

    __syncthreads();

    for (int kt = 0; kt <= qt; kt++) {
        const int k0 = kt * KTILE;

        // Load K (transposed) and V (direct) tiles
        for (int idx = t; idx < KTILE * DH; idx += 128) {
            int j  = idx >> 6;
            int dd = idx & 63;
            size_t g = base + (size_t)(k0 + j) * D_ + dd;
            KsT[dd * PAD + j] = K[g];
            Vs[j * DH + dd]   = V[g];
        }
        __syncthreads();

        // ---- phase 1: scores S = Q K^T ----
        float acc[4][8];
        #pragma unroll
        for (int i = 0; i < 4; i++)
            #pragma unroll
            for (int j = 0; j < 8; j++) acc[i][j] = 0.f;

        #pragma unroll 4
        for (int dd = 0; dd < DH; dd++) {
            float a[4], bb[8];
            #pragma unroll
            for (int i = 0; i < 4; i++) a[i] = QsT[dd * PAD + qg * 4 + i];
            #pragma unroll
            for (int j = 0; j < 8; j++) bb[j] = KsT[dd * PAD + jg * 8 + j];
            #pragma unroll
            for (int i = 0; i < 4; i++)
                #pragma unroll
                for (int j = 0; j < 8; j++)
                    acc[i][j] = fmaf(a[i], bb[j], acc[i][j]);
        }

        const bool diag = (kt == qt);
        #pragma unroll
        for (int i = 0; i < 4; i++) {
            int q = qg * 4 + i;
            #pragma unroll
            for (int j = 0; j < 8; j++) {
                int jj = jg * 8 + j;
                float s = acc[i][j];
                if (diag && jj > q) s = -1e30f;   // strict causal mask
                Ss[q * PAD + jj] = s;
            }
        }
        __syncthreads();

        // ---- phase 2: online softmax + PV ----
        const float* srow = Ss + qi * PAD;
        float mt = m;
        #pragma unroll 8
        for (int j = 0; j < KTILE; j++) mt = fmaxf(mt, srow[j]);

        float corr = __expf(m - mt);   // m=-1e30 initially -> corr=0 (safe)
        m = mt;
        l *= corr;
        #pragma unroll
        for (int i = 0; i < 32; i++) o[i] *= corr;

        const float* vbase = Vs + half * 32;
        for (int j = 0; j < KTILE; j++) {
            float p = __expf(srow[j] - mt);   // masked entries -> exp(-huge)=0
            l += p;
            const float4* v4 = (const float4*)(vbase + j * DH);
            #pragma unroll
            for (int i = 0; i < 8; i++) {
                float4 v = v4[i];
                o[i*4 + 0] = fmaf(p, v.x, o[i*4 + 0]);
                o[i*4 + 1] = fmaf(p, v.y, o[i*4 + 1]);
                o[i*4 + 2] = fmaf(p, v.z, o[i*4 + 2]);
                o[i*4 + 3] = fmaf(p, v.w, o[i*4 + 3]);
            }
        }
        __syncthreads();   // protect K/V/S smem before next tile's loads
    }

    const float inv = 1.f / l;
    float4* orow = (float4*)(O + base + (size_t)(q0 + qi) * D_ + half * 32);
    #pragma unroll
    for (int i = 0; i < 8; i++) {
        float4 v;
        v.x = o[i*4 + 0] * inv;
        v.y = o[i*4 + 1] * inv;
        v.z = o[i*4 + 2] * inv;
        v.w = o[i*4 + 3] * inv;
        orow[i] = v;
    }
}

// ---------------------------------------------------------------------------
extern "C" void kernel_launch(void* const* d_in, const int* in_sizes, int n_in,
                              void* d_out, int out_size)
{
    const float* x  = (const float*)d_in[0];
    const float* Wq = (const float*)d_in[1];
    const float* bq = (const float*)d_in[2];
    const float* Wk = (const float*)d_in[3];
    const float* bk = (const float*)d_in[4];
    const float* Wv = (const float*)d_in[5];
    const float* bv = (const float*)d_in[6];
    const float* Wo = (const float*)d_in[7];
    const float* bo = (const float*)d_in[8];
    float* out = (float*)d_out;

    float *Qp, *Kp, *Vp, *Ap;
    cudaGetSymbolAddress((void**)&Qp, g_Q);
    cudaGetSymbolAddress((void**)&Kp, g_K);
    cudaGetSymbolAddress((void**)&Vp, g_V);
    cudaGetSymbolAddress((void**)&Ap, g_A);

    const int smem_bytes = SMEM_FLOATS * (int)sizeof(float);
    cudaFuncSetAttribute(attn_kernel,
                         cudaFuncAttributeMaxDynamicSharedMemorySize, smem_bytes);

    dim3 ggrid(D_ / 64, M_ / 64);   // (16, 64)
    gemm_bias_kernel<<<ggrid, 256>>>(x, Wq, bq, Qp, M_, D_, D_);
    gemm_bias_kernel<<<ggrid, 256>>>(x, Wk, bk, Kp, M_, D_, D_);
    gemm_bias_kernel<<<ggrid, 256>>>(x, Wv, bv, Vp, M_, D_, D_);

    dim3 agrid(S_ / QTILE, H_, B_);  // (32, 16, 2)
    attn_kernel<<<agrid, 128, smem_bytes>>>(Qp, Kp, Vp, Ap);

    gemm_bias_kernel<<<ggrid, 256>>>(Ap, Wo, bo, out, M_, D_, D_);
}